// round 1
// baseline (speedup 1.0000x reference)
#include <cuda_runtime.h>
#include <math.h>

#define NE    30      // electrons
#define NA    10      // atoms
#define NN    40      // en-graph nodes
#define FEAT  64
#define NPE   435     // ee unique pairs
#define NPN   300     // en unique pairs
#define NL    2
#define T_TAB 4096
#define INV_STEP 256.0f   // T_TAB / 16.0 range
#define BLK   512

// Per-launch filter tables: filt_f(d) = tanh(sum_k exp(-(d-c_k)^2) wf[k,f] + bf[f])
__device__ float g_tab_ee[T_TAB * FEAT];
__device__ float g_tab_en[T_TAB * FEAT];

// ---------------------------------------------------------------------------
// Table build: grid (T_TAB/8, 2), block 256. Each block computes 8 d-rows.
// ---------------------------------------------------------------------------
__global__ void build_tab_kernel(const float* __restrict__ wf_ee,
                                 const float* __restrict__ bf_ee,
                                 const float* __restrict__ wf_en,
                                 const float* __restrict__ bf_en) {
    __shared__ float s_wf[FEAT * FEAT];
    __shared__ float s_rbf[8][FEAT];
    const float* wf = blockIdx.y ? wf_en : wf_ee;
    const float* bf = blockIdx.y ? bf_en : bf_ee;
    float* tab      = blockIdx.y ? g_tab_en : g_tab_ee;

    const int t = threadIdx.x;          // 256 threads
    for (int i = t; i < FEAT * FEAT; i += 256) s_wf[i] = wf[i];

    const int f  = t & 63;
    const int rg = t >> 6;              // 0..3
    const int base = blockIdx.x * 8;

    // fill rbf for rows rg and rg+4
    #pragma unroll
    for (int rr = 0; rr < 2; rr++) {
        int r = rg + rr * 4;
        float d = (float)(base + r) * (1.0f / INV_STEP);
        float x = d - (float)f * (8.0f / 63.0f);
        s_rbf[r][f] = __expf(-x * x);
    }
    __syncthreads();

    float bfv = bf[f];
    float a0 = bfv, a1 = bfv;
    const int r0 = rg, r1 = rg + 4;
    #pragma unroll
    for (int k = 0; k < FEAT; k++) {
        float w = s_wf[k * FEAT + f];
        a0 = fmaf(s_rbf[r0][k], w, a0);
        a1 = fmaf(s_rbf[r1][k], w, a1);
    }
    tab[(base + r0) * FEAT + f] = tanhf(a0);
    tab[(base + r1) * FEAT + f] = tanhf(a1);
}

// ---------------------------------------------------------------------------
// Main kernel: one CTA per batch element. All state in smem; scatter->gather.
// ---------------------------------------------------------------------------
struct Smem {
    float filt[NPE * FEAT];   // 111360 B (reused by en: 300*64)
    float h[NN * FEAT];       // 10240 B
    float agg[NN * FEAT];     // 10240 B
    float wl[NL * FEAT * FEAT]; // 32768 B (current graph's layer weights)
    float bl[NL * FEAT];
    float wr[FEAT];
    float d[NPE];
    float xyz[NE * 3];
    float atm[NA * 3];
    int   pidx[NE * NE];      // ee pair-index LUT
    float red[BLK / 32];
};

__device__ __forceinline__ float block_reduce(float v, float* s_red, int t) {
    #pragma unroll
    for (int o = 16; o; o >>= 1) v += __shfl_down_sync(0xffffffffu, v, o);
    if ((t & 31) == 0) s_red[t >> 5] = v;
    __syncthreads();
    if (t == 0) {
        float x = 0.f;
        #pragma unroll
        for (int w = 0; w < BLK / 32; w++) x += s_red[w];
        s_red[0] = x;
    }
    __syncthreads();
    float r = s_red[0];
    __syncthreads();   // protect s_red for next call / smem reuse
    return r;
}

__global__ void __launch_bounds__(BLK, 1) jastrow_kernel(
    const float* __restrict__ pos,    const float* __restrict__ atoms,
    const float* __restrict__ emb_ee, const float* __restrict__ wl_ee,
    const float* __restrict__ bl_ee,  const float* __restrict__ wr_ee,
    const float* __restrict__ br_ee,
    const float* __restrict__ emb_en, const float* __restrict__ wl_en,
    const float* __restrict__ bl_en,  const float* __restrict__ wr_en,
    const float* __restrict__ br_en,
    float* __restrict__ out) {
    extern __shared__ char smem_raw[];
    Smem& S = *reinterpret_cast<Smem*>(smem_raw);
    const int t = threadIdx.x;
    const int b = blockIdx.x;

    // geometry
    for (int i = t; i < NE * 3; i += BLK) S.xyz[i] = pos[b * NE * 3 + i];
    for (int i = t; i < NA * 3; i += BLK) S.atm[i] = atoms[i];
    // ee layer weights
    for (int i = t; i < NL * FEAT * FEAT; i += BLK) S.wl[i] = wl_ee[i];
    for (int i = t; i < NL * FEAT; i += BLK)        S.bl[i] = bl_ee[i];
    if (t < FEAT) S.wr[t] = wr_ee[t];
    __syncthreads();

    // ================= EE graph =================
    // distances + pair LUT (upper-tri)
    for (int x = t; x < NE * NE; x += BLK) {
        int i = x / NE, j = x % NE;
        if (i < j) {
            int p = (i * (2 * NE - i - 1)) / 2 + (j - i - 1);
            float dx = S.xyz[i * 3 + 0] - S.xyz[j * 3 + 0];
            float dy = S.xyz[i * 3 + 1] - S.xyz[j * 3 + 1];
            float dz = S.xyz[i * 3 + 2] - S.xyz[j * 3 + 2];
            S.d[p] = sqrtf(dx * dx + dy * dy + dz * dz);
            S.pidx[i * NE + j] = p;
            S.pidx[j * NE + i] = p;
        }
    }
    __syncthreads();

    // filt via table lerp
    for (int it = t; it < NPE * FEAT; it += BLK) {
        int p = it >> 6, f = it & 63;
        float u = fminf(S.d[p] * INV_STEP, (float)(T_TAB - 2) + 0.999f);
        int idx = (int)u;
        float w = u - (float)idx;
        float v0 = g_tab_ee[idx * FEAT + f];
        float v1 = g_tab_ee[(idx + 1) * FEAT + f];
        S.filt[it] = fmaf(w, v1 - v0, v0);
    }
    // h init (types: 15x spin-up=0, 15x spin-down=1)
    for (int it = t; it < NE * FEAT; it += BLK) {
        int n = it >> 6, f = it & 63;
        S.h[it] = emb_ee[(n < 15 ? 0 : FEAT) + f];
    }
    __syncthreads();

    for (int l = 0; l < NL; l++) {
        // gather: agg[n,f] = sum_{j!=n} h[j,f] * filt[pair(n,j),f]
        for (int it = t; it < NE * FEAT; it += BLK) {
            int n = it >> 6, f = it & 63;
            float a = 0.f;
            #pragma unroll
            for (int j = 0; j < NE; j++) {
                if (j == n) continue;
                int p = S.pidx[n * NE + j];
                a = fmaf(S.h[j * FEAT + f], S.filt[p * FEAT + f], a);
            }
            S.agg[it] = a;
        }
        __syncthreads();
        // h += tanh(agg @ wl[l] + bl[l])
        for (int it = t; it < NE * FEAT; it += BLK) {
            int n = it >> 6, f = it & 63;
            float a = S.bl[l * FEAT + f];
            const float* wcol = &S.wl[l * FEAT * FEAT + f];
            const float* arow = &S.agg[n * FEAT];
            #pragma unroll
            for (int k = 0; k < FEAT; k++) a = fmaf(arow[k], wcol[k * FEAT], a);
            S.h[it] = S.h[it] + tanhf(a);
        }
        __syncthreads();
    }
    // readout
    float acc = 0.f;
    for (int it = t; it < NE * FEAT; it += BLK) acc = fmaf(S.h[it], S.wr[it & 63], acc);
    float k_ee = block_reduce(acc, S.red, t) + br_ee[0];

    // ================= EN graph =================
    // pair q = a*NE + e  (atom-major, matches reference edge order)
    for (int q = t; q < NPN; q += BLK) {
        int a = q / NE, e = q % NE;
        float dx = S.xyz[e * 3 + 0] - S.atm[a * 3 + 0];
        float dy = S.xyz[e * 3 + 1] - S.atm[a * 3 + 1];
        float dz = S.xyz[e * 3 + 2] - S.atm[a * 3 + 2];
        S.d[q] = sqrtf(dx * dx + dy * dy + dz * dz);
    }
    for (int i = t; i < NL * FEAT * FEAT; i += BLK) S.wl[i] = wl_en[i];
    for (int i = t; i < NL * FEAT; i += BLK)        S.bl[i] = bl_en[i];
    if (t < FEAT) S.wr[t] = wr_en[t];
    __syncthreads();

    for (int it = t; it < NPN * FEAT; it += BLK) {
        int q = it >> 6, f = it & 63;
        float u = fminf(S.d[q] * INV_STEP, (float)(T_TAB - 2) + 0.999f);
        int idx = (int)u;
        float w = u - (float)idx;
        float v0 = g_tab_en[idx * FEAT + f];
        float v1 = g_tab_en[(idx + 1) * FEAT + f];
        S.filt[it] = fmaf(w, v1 - v0, v0);
    }
    // h init: electrons type 0/1, atom a -> type 2+a
    for (int it = t; it < NN * FEAT; it += BLK) {
        int n = it >> 6, f = it & 63;
        int ty = (n < 15) ? 0 : (n < NE ? 1 : 2 + (n - NE));
        S.h[it] = emb_en[ty * FEAT + f];
    }
    __syncthreads();

    for (int l = 0; l < NL; l++) {
        for (int it = t; it < NN * FEAT; it += BLK) {
            int n = it >> 6, f = it & 63;
            float a = 0.f;
            if (n < NE) {  // electron node: neighbors = all atoms
                #pragma unroll
                for (int aa = 0; aa < NA; aa++)
                    a = fmaf(S.h[(NE + aa) * FEAT + f],
                             S.filt[(aa * NE + n) * FEAT + f], a);
            } else {       // atom node: neighbors = all electrons
                int aa = n - NE;
                #pragma unroll
                for (int e = 0; e < NE; e++)
                    a = fmaf(S.h[e * FEAT + f],
                             S.filt[(aa * NE + e) * FEAT + f], a);
            }
            S.agg[it] = a;
        }
        __syncthreads();
        for (int it = t; it < NN * FEAT; it += BLK) {
            int n = it >> 6, f = it & 63;
            float a = S.bl[l * FEAT + f];
            const float* wcol = &S.wl[l * FEAT * FEAT + f];
            const float* arow = &S.agg[n * FEAT];
            #pragma unroll
            for (int k = 0; k < FEAT; k++) a = fmaf(arow[k], wcol[k * FEAT], a);
            S.h[it] = S.h[it] + tanhf(a);
        }
        __syncthreads();
    }
    float acc2 = 0.f;
    for (int it = t; it < NN * FEAT; it += BLK) acc2 = fmaf(S.h[it], S.wr[it & 63], acc2);
    float k_en = block_reduce(acc2, S.red, t) + br_en[0];

    if (t == 0) out[b] = expf(k_ee + k_en);
}

// ---------------------------------------------------------------------------
extern "C" void kernel_launch(void* const* d_in, const int* in_sizes, int n_in,
                              void* d_out, int out_size) {
    const float* pos    = (const float*)d_in[0];
    const float* atoms  = (const float*)d_in[1];
    const float* emb_ee = (const float*)d_in[2];
    const float* wf_ee  = (const float*)d_in[3];
    const float* bf_ee  = (const float*)d_in[4];
    const float* wl_ee  = (const float*)d_in[5];
    const float* bl_ee  = (const float*)d_in[6];
    const float* wr_ee  = (const float*)d_in[7];
    const float* br_ee  = (const float*)d_in[8];
    const float* emb_en = (const float*)d_in[9];
    const float* wf_en  = (const float*)d_in[10];
    const float* bf_en  = (const float*)d_in[11];
    const float* wl_en  = (const float*)d_in[12];
    const float* bl_en  = (const float*)d_in[13];
    const float* wr_en  = (const float*)d_in[14];
    const float* br_en  = (const float*)d_in[15];
    float* out = (float*)d_out;

    int nb = in_sizes[0] / (NE * 3);

    cudaFuncSetAttribute(jastrow_kernel,
                         cudaFuncAttributeMaxDynamicSharedMemorySize,
                         (int)sizeof(Smem));

    build_tab_kernel<<<dim3(T_TAB / 8, 2), 256>>>(wf_ee, bf_ee, wf_en, bf_en);
    jastrow_kernel<<<nb, BLK, sizeof(Smem)>>>(
        pos, atoms, emb_ee, wl_ee, bl_ee, wr_ee, br_ee,
        emb_en, wl_en, bl_en, wr_en, br_en, out);
}

// round 2
// speedup vs baseline: 1.4628x; 1.4628x over previous
#include <cuda_runtime.h>
#include <cuda_fp16.h>
#include <math.h>

#define NE    30      // electrons
#define NA    10      // atoms
#define NN    40      // en-graph nodes
#define FEAT  64
#define NPE   435     // ee unique pairs
#define NPN   300     // en unique pairs
#define NL    2
#define T_TAB 4096
#define INV_STEP 256.0f   // T_TAB / 16.0 range
#define BLK   512

// Per-launch filter tables: filt_f(d) = tanh(sum_k exp(-(d-c_k)^2) wf[k,f] + bf[f])
__device__ float g_tab_ee[T_TAB * FEAT];
__device__ float g_tab_en[T_TAB * FEAT];

// ---------------------------------------------------------------------------
// Table build: grid (T_TAB/8, 2), block 256. Each block computes 8 d-rows.
// ---------------------------------------------------------------------------
__global__ void build_tab_kernel(const float* __restrict__ wf_ee,
                                 const float* __restrict__ bf_ee,
                                 const float* __restrict__ wf_en,
                                 const float* __restrict__ bf_en) {
    __shared__ float s_wf[FEAT * FEAT];
    __shared__ float s_rbf[8][FEAT];
    const float* wf = blockIdx.y ? wf_en : wf_ee;
    const float* bf = blockIdx.y ? bf_en : bf_ee;
    float* tab      = blockIdx.y ? g_tab_en : g_tab_ee;

    const int t = threadIdx.x;          // 256 threads
    for (int i = t; i < FEAT * FEAT; i += 256) s_wf[i] = wf[i];

    const int f  = t & 63;
    const int rg = t >> 6;              // 0..3
    const int base = blockIdx.x * 8;

    #pragma unroll
    for (int rr = 0; rr < 2; rr++) {
        int r = rg + rr * 4;
        float d = (float)(base + r) * (1.0f / INV_STEP);
        float x = d - (float)f * (8.0f / 63.0f);
        s_rbf[r][f] = __expf(-x * x);
    }
    __syncthreads();

    float bfv = bf[f];
    float a0 = bfv, a1 = bfv;
    const int r0 = rg, r1 = rg + 4;
    #pragma unroll
    for (int k = 0; k < FEAT; k++) {
        float w = s_wf[k * FEAT + f];
        a0 = fmaf(s_rbf[r0][k], w, a0);
        a1 = fmaf(s_rbf[r1][k], w, a1);
    }
    tab[(base + r0) * FEAT + f] = tanhf(a0);
    tab[(base + r1) * FEAT + f] = tanhf(a1);
}

// ---------------------------------------------------------------------------
// Main kernel: one CTA per batch element, 2 CTAs/SM.
// filt in fp16 (half2 per feature-pair); d[] aliased onto agg[].
// ---------------------------------------------------------------------------
struct Smem {
    __half2 filt2[NPE * 32];   // 55,680 B (en uses first 300*32)
    float   h[NN * FEAT];      // 10,240
    float   agg[NN * FEAT];    // 10,240  (also scratch for d[] before gathers)
    float   wl[NL * FEAT * FEAT]; // 32,768
    float   bl[NL * FEAT];     // 512
    float   wr[FEAT];          // 256
    float   xyz[NE * 3];       // 360
    float   atm[NA * 3];       // 120
    short   pidx[NE * NE];     // 1,800
    float   red[BLK / 32];     // 64
};                              // total 112,040 B -> 2 CTAs/SM

__device__ __forceinline__ float block_reduce(float v, float* s_red, int t) {
    #pragma unroll
    for (int o = 16; o; o >>= 1) v += __shfl_down_sync(0xffffffffu, v, o);
    if ((t & 31) == 0) s_red[t >> 5] = v;
    __syncthreads();
    if (t == 0) {
        float x = 0.f;
        #pragma unroll
        for (int w = 0; w < BLK / 32; w++) x += s_red[w];
        s_red[0] = x;
    }
    __syncthreads();
    float r = s_red[0];
    __syncthreads();
    return r;
}

__global__ void __launch_bounds__(BLK, 2) jastrow_kernel(
    const float* __restrict__ pos,    const float* __restrict__ atoms,
    const float* __restrict__ emb_ee, const float* __restrict__ wl_ee,
    const float* __restrict__ bl_ee,  const float* __restrict__ wr_ee,
    const float* __restrict__ br_ee,
    const float* __restrict__ emb_en, const float* __restrict__ wl_en,
    const float* __restrict__ bl_en,  const float* __restrict__ wr_en,
    const float* __restrict__ br_en,
    float* __restrict__ out) {
    extern __shared__ char smem_raw[];
    Smem& S = *reinterpret_cast<Smem*>(smem_raw);
    float* Sd = S.agg;   // scratch distances, dead once filt2 is built
    const int t = threadIdx.x;
    const int b = blockIdx.x;

    for (int i = t; i < NE * 3; i += BLK) S.xyz[i] = pos[b * NE * 3 + i];
    for (int i = t; i < NA * 3; i += BLK) S.atm[i] = atoms[i];
    for (int i = t; i < NL * FEAT * FEAT; i += BLK) S.wl[i] = wl_ee[i];
    for (int i = t; i < NL * FEAT; i += BLK)        S.bl[i] = bl_ee[i];
    if (t < FEAT) S.wr[t] = wr_ee[t];
    __syncthreads();

    // ================= EE graph =================
    for (int x = t; x < NE * NE; x += BLK) {
        int i = x / NE, j = x % NE;
        if (i < j) {
            int p = (i * (2 * NE - i - 1)) / 2 + (j - i - 1);
            float dx = S.xyz[i * 3 + 0] - S.xyz[j * 3 + 0];
            float dy = S.xyz[i * 3 + 1] - S.xyz[j * 3 + 1];
            float dz = S.xyz[i * 3 + 2] - S.xyz[j * 3 + 2];
            Sd[p] = sqrtf(dx * dx + dy * dy + dz * dz);
            S.pidx[i * NE + j] = (short)p;
            S.pidx[j * NE + i] = (short)p;
        }
    }
    __syncthreads();

    // filt via table lerp -> half2 (feature pairs)
    for (int it = t; it < NPE * 32; it += BLK) {
        int p = it >> 5, fp = it & 31;
        float u = fminf(Sd[p] * INV_STEP, (float)(T_TAB - 2) + 0.999f);
        int idx = (int)u;
        float w = u - (float)idx;
        float2 v0 = *(const float2*)&g_tab_ee[idx * FEAT + 2 * fp];
        float2 v1 = *(const float2*)&g_tab_ee[(idx + 1) * FEAT + 2 * fp];
        float rx = fmaf(w, v1.x - v0.x, v0.x);
        float ry = fmaf(w, v1.y - v0.y, v0.y);
        S.filt2[it] = __floats2half2_rn(rx, ry);
    }
    for (int it = t; it < NE * FEAT; it += BLK) {
        int n = it >> 6, f = it & 63;
        S.h[it] = emb_ee[(n < 15 ? 0 : FEAT) + f];
    }
    __syncthreads();

    for (int l = 0; l < NL; l++) {
        // gather: agg[n,2fp..] = sum_{j!=n} h[j,..] * filt[pair(n,j),..]
        for (int it = t; it < NE * 32; it += BLK) {
            int n = it >> 5, fp = it & 31;
            float ax0 = 0.f, ay0 = 0.f, ax1 = 0.f, ay1 = 0.f;
            #pragma unroll
            for (int j = 0; j < NE; j++) {
                if (j == n) continue;
                int p = (int)S.pidx[n * NE + j];
                float2 hv = *(const float2*)&S.h[j * FEAT + 2 * fp];
                float2 fv = __half22float2(S.filt2[p * 32 + fp]);
                if (j & 1) { ax1 = fmaf(hv.x, fv.x, ax1); ay1 = fmaf(hv.y, fv.y, ay1); }
                else       { ax0 = fmaf(hv.x, fv.x, ax0); ay0 = fmaf(hv.y, fv.y, ay0); }
            }
            float2 a; a.x = ax0 + ax1; a.y = ay0 + ay1;
            *(float2*)&S.agg[n * FEAT + 2 * fp] = a;
        }
        __syncthreads();
        // h += tanh(agg @ wl[l] + bl[l])
        for (int it = t; it < NE * 32; it += BLK) {
            int n = it >> 5, fp = it & 31;
            float ax0 = S.bl[l * FEAT + 2 * fp], ay0 = S.bl[l * FEAT + 2 * fp + 1];
            float ax1 = 0.f, ay1 = 0.f;
            const float* wbase = &S.wl[l * FEAT * FEAT + 2 * fp];
            const float* arow = &S.agg[n * FEAT];
            #pragma unroll 16
            for (int k = 0; k < FEAT; k += 2) {
                float a0 = arow[k], a1 = arow[k + 1];
                float2 w0 = *(const float2*)&wbase[k * FEAT];
                float2 w1 = *(const float2*)&wbase[(k + 1) * FEAT];
                ax0 = fmaf(a0, w0.x, ax0); ay0 = fmaf(a0, w0.y, ay0);
                ax1 = fmaf(a1, w1.x, ax1); ay1 = fmaf(a1, w1.y, ay1);
            }
            int o = n * FEAT + 2 * fp;
            S.h[o]     += tanhf(ax0 + ax1);
            S.h[o + 1] += tanhf(ay0 + ay1);
        }
        __syncthreads();
    }
    float acc = 0.f;
    for (int it = t; it < NE * FEAT; it += BLK) acc = fmaf(S.h[it], S.wr[it & 63], acc);
    float k_ee = block_reduce(acc, S.red, t) + br_ee[0];

    // ================= EN graph =================
    for (int q = t; q < NPN; q += BLK) {
        int a = q / NE, e = q % NE;
        float dx = S.xyz[e * 3 + 0] - S.atm[a * 3 + 0];
        float dy = S.xyz[e * 3 + 1] - S.atm[a * 3 + 1];
        float dz = S.xyz[e * 3 + 2] - S.atm[a * 3 + 2];
        Sd[q] = sqrtf(dx * dx + dy * dy + dz * dz);
    }
    for (int i = t; i < NL * FEAT * FEAT; i += BLK) S.wl[i] = wl_en[i];
    for (int i = t; i < NL * FEAT; i += BLK)        S.bl[i] = bl_en[i];
    if (t < FEAT) S.wr[t] = wr_en[t];
    __syncthreads();

    for (int it = t; it < NPN * 32; it += BLK) {
        int q = it >> 5, fp = it & 31;
        float u = fminf(Sd[q] * INV_STEP, (float)(T_TAB - 2) + 0.999f);
        int idx = (int)u;
        float w = u - (float)idx;
        float2 v0 = *(const float2*)&g_tab_en[idx * FEAT + 2 * fp];
        float2 v1 = *(const float2*)&g_tab_en[(idx + 1) * FEAT + 2 * fp];
        float rx = fmaf(w, v1.x - v0.x, v0.x);
        float ry = fmaf(w, v1.y - v0.y, v0.y);
        S.filt2[it] = __floats2half2_rn(rx, ry);
    }
    for (int it = t; it < NN * FEAT; it += BLK) {
        int n = it >> 6, f = it & 63;
        int ty = (n < 15) ? 0 : (n < NE ? 1 : 2 + (n - NE));
        S.h[it] = emb_en[ty * FEAT + f];
    }
    __syncthreads();

    for (int l = 0; l < NL; l++) {
        for (int it = t; it < NN * 32; it += BLK) {
            int n = it >> 5, fp = it & 31;
            float ax0 = 0.f, ay0 = 0.f, ax1 = 0.f, ay1 = 0.f;
            if (n < NE) {  // electron node: neighbors = all atoms
                #pragma unroll
                for (int aa = 0; aa < NA; aa++) {
                    float2 hv = *(const float2*)&S.h[(NE + aa) * FEAT + 2 * fp];
                    float2 fv = __half22float2(S.filt2[(aa * NE + n) * 32 + fp]);
                    if (aa & 1) { ax1 = fmaf(hv.x, fv.x, ax1); ay1 = fmaf(hv.y, fv.y, ay1); }
                    else        { ax0 = fmaf(hv.x, fv.x, ax0); ay0 = fmaf(hv.y, fv.y, ay0); }
                }
            } else {       // atom node: neighbors = all electrons
                int aa = n - NE;
                #pragma unroll
                for (int e = 0; e < NE; e++) {
                    float2 hv = *(const float2*)&S.h[e * FEAT + 2 * fp];
                    float2 fv = __half22float2(S.filt2[(aa * NE + e) * 32 + fp]);
                    if (e & 1) { ax1 = fmaf(hv.x, fv.x, ax1); ay1 = fmaf(hv.y, fv.y, ay1); }
                    else       { ax0 = fmaf(hv.x, fv.x, ax0); ay0 = fmaf(hv.y, fv.y, ay0); }
                }
            }
            float2 a; a.x = ax0 + ax1; a.y = ay0 + ay1;
            *(float2*)&S.agg[n * FEAT + 2 * fp] = a;
        }
        __syncthreads();
        for (int it = t; it < NN * 32; it += BLK) {
            int n = it >> 5, fp = it & 31;
            float ax0 = S.bl[l * FEAT + 2 * fp], ay0 = S.bl[l * FEAT + 2 * fp + 1];
            float ax1 = 0.f, ay1 = 0.f;
            const float* wbase = &S.wl[l * FEAT * FEAT + 2 * fp];
            const float* arow = &S.agg[n * FEAT];
            #pragma unroll 16
            for (int k = 0; k < FEAT; k += 2) {
                float a0 = arow[k], a1 = arow[k + 1];
                float2 w0 = *(const float2*)&wbase[k * FEAT];
                float2 w1 = *(const float2*)&wbase[(k + 1) * FEAT];
                ax0 = fmaf(a0, w0.x, ax0); ay0 = fmaf(a0, w0.y, ay0);
                ax1 = fmaf(a1, w1.x, ax1); ay1 = fmaf(a1, w1.y, ay1);
            }
            int o = n * FEAT + 2 * fp;
            S.h[o]     += tanhf(ax0 + ax1);
            S.h[o + 1] += tanhf(ay0 + ay1);
        }
        __syncthreads();
    }
    float acc2 = 0.f;
    for (int it = t; it < NN * FEAT; it += BLK) acc2 = fmaf(S.h[it], S.wr[it & 63], acc2);
    float k_en = block_reduce(acc2, S.red, t) + br_en[0];

    if (t == 0) out[b] = expf(k_ee + k_en);
}

// ---------------------------------------------------------------------------
extern "C" void kernel_launch(void* const* d_in, const int* in_sizes, int n_in,
                              void* d_out, int out_size) {
    const float* pos    = (const float*)d_in[0];
    const float* atoms  = (const float*)d_in[1];
    const float* emb_ee = (const float*)d_in[2];
    const float* wf_ee  = (const float*)d_in[3];
    const float* bf_ee  = (const float*)d_in[4];
    const float* wl_ee  = (const float*)d_in[5];
    const float* bl_ee  = (const float*)d_in[6];
    const float* wr_ee  = (const float*)d_in[7];
    const float* br_ee  = (const float*)d_in[8];
    const float* emb_en = (const float*)d_in[9];
    const float* wf_en  = (const float*)d_in[10];
    const float* bf_en  = (const float*)d_in[11];
    const float* wl_en  = (const float*)d_in[12];
    const float* bl_en  = (const float*)d_in[13];
    const float* wr_en  = (const float*)d_in[14];
    const float* br_en  = (const float*)d_in[15];
    float* out = (float*)d_out;

    int nb = in_sizes[0] / (NE * 3);

    cudaFuncSetAttribute(jastrow_kernel,
                         cudaFuncAttributeMaxDynamicSharedMemorySize,
                         (int)sizeof(Smem));

    build_tab_kernel<<<dim3(T_TAB / 8, 2), 256>>>(wf_ee, bf_ee, wf_en, bf_en);
    jastrow_kernel<<<nb, BLK, sizeof(Smem)>>>(
        pos, atoms, emb_ee, wl_ee, bl_ee, wr_ee, br_ee,
        emb_en, wl_en, bl_en, wr_en, br_en, out);
}

// round 3
// speedup vs baseline: 1.7653x; 1.2068x over previous
#include <cuda_runtime.h>
#include <cuda_fp16.h>
#include <math.h>

#define NE    30      // electrons
#define NA    10      // atoms
#define NN    40      // en-graph nodes
#define FEAT  64
#define NPE   435     // ee unique pairs
#define NPN   300     // en unique pairs
#define NL    2
#define T_TAB 4096
#define INV_STEP 256.0f   // T_TAB / 16.0 range
#define BLK   512
#define NWARP (BLK / 32)

typedef unsigned long long u64;

// Per-launch filter tables: filt_f(d) = tanh(sum_k exp(-(d-c_k)^2) wf[k,f] + bf[f])
__device__ float g_tab_ee[T_TAB * FEAT];
__device__ float g_tab_en[T_TAB * FEAT];

// ---- packed f32x2 helpers (Blackwell) -------------------------------------
__device__ __forceinline__ u64 pack2(float x, float y) {
    u64 r; asm("mov.b64 %0, {%1,%2};" : "=l"(r) : "f"(x), "f"(y)); return r;
}
__device__ __forceinline__ float2 unpack2(u64 v) {
    float2 f; asm("mov.b64 {%0,%1}, %2;" : "=f"(f.x), "=f"(f.y) : "l"(v)); return f;
}
#define FMA2(d, a, b, c) asm("fma.rn.f32x2 %0, %1, %2, %3;" : "=l"(d) : "l"(a), "l"(b), "l"(c))
#define ADD2(d, a, b)    asm("add.rn.f32x2 %0, %1, %2;"     : "=l"(d) : "l"(a), "l"(b))

__device__ __forceinline__ float tanh_fast(float x) {
    float cx = fminf(fmaxf(x, -15.f), 15.f);
    float e = __expf(2.f * cx);
    return __fdividef(e - 1.f, e + 1.f);
}

// upper-tri pair index for i!=j, 0<=i,j<NE
__device__ __forceinline__ int pair_idx(int n, int j) {
    int a = min(n, j), b = n + j - a;
    return ((a * (2 * NE - 1 - a)) >> 1) + b - a - 1;
}

// ---------------------------------------------------------------------------
// Table build: grid (T_TAB/8, 2), block 256.
// ---------------------------------------------------------------------------
__global__ void build_tab_kernel(const float* __restrict__ wf_ee,
                                 const float* __restrict__ bf_ee,
                                 const float* __restrict__ wf_en,
                                 const float* __restrict__ bf_en) {
    __shared__ float s_wf[FEAT * FEAT];
    __shared__ float s_rbf[8][FEAT];
    const float* wf = blockIdx.y ? wf_en : wf_ee;
    const float* bf = blockIdx.y ? bf_en : bf_ee;
    float* tab      = blockIdx.y ? g_tab_en : g_tab_ee;

    const int t = threadIdx.x;
    for (int i = t; i < FEAT * FEAT; i += 256) s_wf[i] = wf[i];

    const int f  = t & 63;
    const int rg = t >> 6;
    const int base = blockIdx.x * 8;

    #pragma unroll
    for (int rr = 0; rr < 2; rr++) {
        int r = rg + rr * 4;
        float d = (float)(base + r) * (1.0f / INV_STEP);
        float x = d - (float)f * (8.0f / 63.0f);
        s_rbf[r][f] = __expf(-x * x);
    }
    __syncthreads();

    float bfv = bf[f];
    float a0 = bfv, a1 = bfv;
    const int r0 = rg, r1 = rg + 4;
    #pragma unroll
    for (int k = 0; k < FEAT; k++) {
        float w = s_wf[k * FEAT + f];
        a0 = fmaf(s_rbf[r0][k], w, a0);
        a1 = fmaf(s_rbf[r1][k], w, a1);
    }
    tab[(base + r0) * FEAT + f] = tanhf(a0);
    tab[(base + r1) * FEAT + f] = tanhf(a1);
}

// ---------------------------------------------------------------------------
struct Smem {
    __half2 filt2[NPE * 32];      // 55,680 B (en uses first 300*32)
    float   h[NN * FEAT];         // 10,240
    float   agg[NN * FEAT];       // 10,240  (also scratch for d[])
    float   wl[NL * FEAT * FEAT]; // 32,768
    float   bl[NL * FEAT];        // 512
    float   wr[FEAT];             // 256
    float   xyz[NE * 3];          // 360
    float   atm[NA * 3];          // 120
    float   red[NWARP];           // 64
};                                 // ~110,240 B -> 2 CTAs/SM

__device__ __forceinline__ float block_reduce(float v, float* s_red, int t) {
    #pragma unroll
    for (int o = 16; o; o >>= 1) v += __shfl_down_sync(0xffffffffu, v, o);
    if ((t & 31) == 0) s_red[t >> 5] = v;
    __syncthreads();
    if (t == 0) {
        float x = 0.f;
        #pragma unroll
        for (int w = 0; w < NWARP; w++) x += s_red[w];
        s_red[0] = x;
    }
    __syncthreads();
    float r = s_red[0];
    __syncthreads();
    return r;
}

// linear layer for node pair (n0, n1): h[n] += tanh(agg[n] @ wl + bl)
__device__ __forceinline__ void linear_pair(Smem& S, int l, int n0, int n1, int fp) {
    const float* wbase = &S.wl[l * FEAT * FEAT + 2 * fp];
    u64 bias = *(const u64*)&S.bl[l * FEAT + 2 * fp];
    u64 acc0a = bias, acc0b = 0, acc1a = bias, acc1b = 0;
    const float* ar0 = &S.agg[n0 * FEAT];
    const float* ar1 = &S.agg[n1 * FEAT];
    #pragma unroll
    for (int k = 0; k < FEAT; k += 2) {
        u64 w0 = *(const u64*)&wbase[k * FEAT];
        u64 w1 = *(const u64*)&wbase[(k + 1) * FEAT];
        float2 a0 = unpack2(*(const u64*)&ar0[k]);   // broadcast
        float2 a1 = unpack2(*(const u64*)&ar1[k]);
        u64 d;
        d = pack2(a0.x, a0.x); FMA2(acc0a, d, w0, acc0a);
        d = pack2(a0.y, a0.y); FMA2(acc0b, d, w1, acc0b);
        d = pack2(a1.x, a1.x); FMA2(acc1a, d, w0, acc1a);
        d = pack2(a1.y, a1.y); FMA2(acc1b, d, w1, acc1b);
    }
    ADD2(acc0a, acc0a, acc0b);
    ADD2(acc1a, acc1a, acc1b);
    float2 s0 = unpack2(acc0a), s1 = unpack2(acc1a);
    float2 h0 = unpack2(*(const u64*)&S.h[n0 * FEAT + 2 * fp]);
    float2 h1 = unpack2(*(const u64*)&S.h[n1 * FEAT + 2 * fp]);
    h0.x += tanh_fast(s0.x); h0.y += tanh_fast(s0.y);
    h1.x += tanh_fast(s1.x); h1.y += tanh_fast(s1.y);
    *(u64*)&S.h[n0 * FEAT + 2 * fp] = pack2(h0.x, h0.y);
    *(u64*)&S.h[n1 * FEAT + 2 * fp] = pack2(h1.x, h1.y);
}

__global__ void __launch_bounds__(BLK, 2) jastrow_kernel(
    const float* __restrict__ pos,    const float* __restrict__ atoms,
    const float* __restrict__ emb_ee, const float* __restrict__ wl_ee,
    const float* __restrict__ bl_ee,  const float* __restrict__ wr_ee,
    const float* __restrict__ br_ee,
    const float* __restrict__ emb_en, const float* __restrict__ wl_en,
    const float* __restrict__ bl_en,  const float* __restrict__ wr_en,
    const float* __restrict__ br_en,
    float* __restrict__ out) {
    extern __shared__ char smem_raw[];
    Smem& S = *reinterpret_cast<Smem*>(smem_raw);
    float* Sd = S.agg;   // scratch distances, dead once filt2 is built
    const int t = threadIdx.x;
    const int b = blockIdx.x;
    const int warp = t >> 5;
    const int fp = t & 31;

    for (int i = t; i < NE * 3; i += BLK) S.xyz[i] = pos[b * NE * 3 + i];
    for (int i = t; i < NA * 3; i += BLK) S.atm[i] = atoms[i];
    for (int i = t; i < NL * FEAT * FEAT; i += BLK) S.wl[i] = wl_ee[i];
    for (int i = t; i < NL * FEAT; i += BLK)        S.bl[i] = bl_ee[i];
    if (t < FEAT) S.wr[t] = wr_ee[t];
    __syncthreads();

    // ================= EE graph =================
    for (int x = t; x < NE * NE; x += BLK) {
        int i = x / NE, j = x % NE;
        if (i < j) {
            int p = pair_idx(i, j);
            float dx = S.xyz[i * 3 + 0] - S.xyz[j * 3 + 0];
            float dy = S.xyz[i * 3 + 1] - S.xyz[j * 3 + 1];
            float dz = S.xyz[i * 3 + 2] - S.xyz[j * 3 + 2];
            Sd[p] = sqrtf(dx * dx + dy * dy + dz * dz);
        }
    }
    __syncthreads();

    // filt via table lerp -> half2
    for (int it = t; it < NPE * 32; it += BLK) {
        int p = it >> 5, f2 = it & 31;
        float u = fminf(Sd[p] * INV_STEP, (float)(T_TAB - 2) + 0.999f);
        int idx = (int)u;
        float w = u - (float)idx;
        float2 v0 = *(const float2*)&g_tab_ee[idx * FEAT + 2 * f2];
        float2 v1 = *(const float2*)&g_tab_ee[(idx + 1) * FEAT + 2 * f2];
        float rx = fmaf(w, v1.x - v0.x, v0.x);
        float ry = fmaf(w, v1.y - v0.y, v0.y);
        S.filt2[it] = __floats2half2_rn(rx, ry);
    }
    for (int it = t; it < NE * FEAT; it += BLK) {
        int n = it >> 6, f = it & 63;
        S.h[it] = emb_ee[(n < 15 ? 0 : FEAT) + f];
    }
    __syncthreads();

    for (int l = 0; l < NL; l++) {
        // gather: 15 node-pairs across 16 warps
        if (warp < 15) {
            const int n0 = 2 * warp, n1 = n0 + 1;
            u64 a0a = 0, a0b = 0, a1a = 0, a1b = 0;
            #pragma unroll
            for (int j = 0; j < NE; j++) {
                u64 hv = *(const u64*)&S.h[j * FEAT + 2 * fp];
                if (j != n0) {
                    float2 fv = __half22float2(S.filt2[pair_idx(n0, j) * 32 + fp]);
                    u64 f2 = pack2(fv.x, fv.y);
                    if (j & 1) { FMA2(a0b, hv, f2, a0b); } else { FMA2(a0a, hv, f2, a0a); }
                }
                if (j != n1) {
                    float2 fv = __half22float2(S.filt2[pair_idx(n1, j) * 32 + fp]);
                    u64 f2 = pack2(fv.x, fv.y);
                    if (j & 1) { FMA2(a1b, hv, f2, a1b); } else { FMA2(a1a, hv, f2, a1a); }
                }
            }
            ADD2(a0a, a0a, a0b);
            ADD2(a1a, a1a, a1b);
            *(u64*)&S.agg[n0 * FEAT + 2 * fp] = a0a;
            *(u64*)&S.agg[n1 * FEAT + 2 * fp] = a1a;
        }
        __syncthreads();
        if (warp < 15) linear_pair(S, l, 2 * warp, 2 * warp + 1, fp);
        __syncthreads();
    }
    float acc = 0.f;
    for (int it = t; it < NE * FEAT; it += BLK) acc = fmaf(S.h[it], S.wr[it & 63], acc);
    float k_ee = block_reduce(acc, S.red, t) + br_ee[0];

    // ================= EN graph =================
    for (int q = t; q < NPN; q += BLK) {
        int a = q / NE, e = q % NE;
        float dx = S.xyz[e * 3 + 0] - S.atm[a * 3 + 0];
        float dy = S.xyz[e * 3 + 1] - S.atm[a * 3 + 1];
        float dz = S.xyz[e * 3 + 2] - S.atm[a * 3 + 2];
        Sd[q] = sqrtf(dx * dx + dy * dy + dz * dz);
    }
    for (int i = t; i < NL * FEAT * FEAT; i += BLK) S.wl[i] = wl_en[i];
    for (int i = t; i < NL * FEAT; i += BLK)        S.bl[i] = bl_en[i];
    if (t < FEAT) S.wr[t] = wr_en[t];
    __syncthreads();

    for (int it = t; it < NPN * 32; it += BLK) {
        int q = it >> 5, f2 = it & 31;
        float u = fminf(Sd[q] * INV_STEP, (float)(T_TAB - 2) + 0.999f);
        int idx = (int)u;
        float w = u - (float)idx;
        float2 v0 = *(const float2*)&g_tab_en[idx * FEAT + 2 * f2];
        float2 v1 = *(const float2*)&g_tab_en[(idx + 1) * FEAT + 2 * f2];
        float rx = fmaf(w, v1.x - v0.x, v0.x);
        float ry = fmaf(w, v1.y - v0.y, v0.y);
        S.filt2[it] = __floats2half2_rn(rx, ry);
    }
    for (int it = t; it < NN * FEAT; it += BLK) {
        int n = it >> 6, f = it & 63;
        int ty = (n < 15) ? 0 : (n < NE ? 1 : 2 + (n - NE));
        S.h[it] = emb_en[ty * FEAT + f];
    }
    __syncthreads();

    for (int l = 0; l < NL; l++) {
        // gather: 20 node-pairs (15 electron pairs + 5 atom pairs)
        for (int item = warp; item < 20; item += NWARP) {
            u64 a0a = 0, a0b = 0, a1a = 0, a1b = 0;
            int n0, n1;
            if (item < 15) {          // electron pair: neighbors = atoms
                n0 = 2 * item; n1 = n0 + 1;
                #pragma unroll
                for (int aa = 0; aa < NA; aa++) {
                    u64 hv = *(const u64*)&S.h[(NE + aa) * FEAT + 2 * fp];
                    float2 f0 = __half22float2(S.filt2[(aa * NE + n0) * 32 + fp]);
                    float2 f1 = __half22float2(S.filt2[(aa * NE + n1) * 32 + fp]);
                    u64 p0 = pack2(f0.x, f0.y), p1 = pack2(f1.x, f1.y);
                    if (aa & 1) { FMA2(a0b, hv, p0, a0b); FMA2(a1b, hv, p1, a1b); }
                    else        { FMA2(a0a, hv, p0, a0a); FMA2(a1a, hv, p1, a1a); }
                }
            } else {                  // atom pair: neighbors = electrons
                int aa0 = 2 * (item - 15), aa1 = aa0 + 1;
                n0 = NE + aa0; n1 = NE + aa1;
                #pragma unroll
                for (int e = 0; e < NE; e++) {
                    u64 hv = *(const u64*)&S.h[e * FEAT + 2 * fp];
                    float2 f0 = __half22float2(S.filt2[(aa0 * NE + e) * 32 + fp]);
                    float2 f1 = __half22float2(S.filt2[(aa1 * NE + e) * 32 + fp]);
                    u64 p0 = pack2(f0.x, f0.y), p1 = pack2(f1.x, f1.y);
                    if (e & 1) { FMA2(a0b, hv, p0, a0b); FMA2(a1b, hv, p1, a1b); }
                    else       { FMA2(a0a, hv, p0, a0a); FMA2(a1a, hv, p1, a1a); }
                }
            }
            ADD2(a0a, a0a, a0b);
            ADD2(a1a, a1a, a1b);
            *(u64*)&S.agg[n0 * FEAT + 2 * fp] = a0a;
            *(u64*)&S.agg[n1 * FEAT + 2 * fp] = a1a;
        }
        __syncthreads();
        for (int item = warp; item < 20; item += NWARP)
            linear_pair(S, l, 2 * item, 2 * item + 1, fp);
        __syncthreads();
    }
    float acc2 = 0.f;
    for (int it = t; it < NN * FEAT; it += BLK) acc2 = fmaf(S.h[it], S.wr[it & 63], acc2);
    float k_en = block_reduce(acc2, S.red, t) + br_en[0];

    if (t == 0) out[b] = expf(k_ee + k_en);
}

// ---------------------------------------------------------------------------
extern "C" void kernel_launch(void* const* d_in, const int* in_sizes, int n_in,
                              void* d_out, int out_size) {
    const float* pos    = (const float*)d_in[0];
    const float* atoms  = (const float*)d_in[1];
    const float* emb_ee = (const float*)d_in[2];
    const float* wf_ee  = (const float*)d_in[3];
    const float* bf_ee  = (const float*)d_in[4];
    const float* wl_ee  = (const float*)d_in[5];
    const float* bl_ee  = (const float*)d_in[6];
    const float* wr_ee  = (const float*)d_in[7];
    const float* br_ee  = (const float*)d_in[8];
    const float* emb_en = (const float*)d_in[9];
    const float* wf_en  = (const float*)d_in[10];
    const float* bf_en  = (const float*)d_in[11];
    const float* wl_en  = (const float*)d_in[12];
    const float* bl_en  = (const float*)d_in[13];
    const float* wr_en  = (const float*)d_in[14];
    const float* br_en  = (const float*)d_in[15];
    float* out = (float*)d_out;

    int nb = in_sizes[0] / (NE * 3);

    cudaFuncSetAttribute(jastrow_kernel,
                         cudaFuncAttributeMaxDynamicSharedMemorySize,
                         (int)sizeof(Smem));

    build_tab_kernel<<<dim3(T_TAB / 8, 2), 256>>>(wf_ee, bf_ee, wf_en, bf_en);
    jastrow_kernel<<<nb, BLK, sizeof(Smem)>>>(
        pos, atoms, emb_ee, wl_ee, bl_ee, wr_ee, br_ee,
        emb_en, wl_en, bl_en, wr_en, br_en, out);
}

// round 4
// speedup vs baseline: 1.9015x; 1.0771x over previous
#include <cuda_runtime.h>
#include <cuda_fp16.h>
#include <math.h>

#define NE    30      // electrons
#define NA    10      // atoms
#define NN    40      // en-graph nodes
#define FEAT  64
#define NPE   435     // ee unique pairs
#define NPN   300     // en unique pairs
#define NL    2
#define T_TAB 4096
#define INV_STEP 256.0f   // T_TAB / 16.0 range
#define BLK   512
#define NWARP (BLK / 32)

typedef unsigned long long u64;

__device__ float g_tab_ee[T_TAB * FEAT];
__device__ float g_tab_en[T_TAB * FEAT];

// ---- packed f32x2 helpers (Blackwell) -------------------------------------
__device__ __forceinline__ u64 pack2(float x, float y) {
    u64 r; asm("mov.b64 %0, {%1,%2};" : "=l"(r) : "f"(x), "f"(y)); return r;
}
__device__ __forceinline__ float2 unpack2(u64 v) {
    float2 f; asm("mov.b64 {%0,%1}, %2;" : "=f"(f.x), "=f"(f.y) : "l"(v)); return f;
}
#define FMA2(d, a, b, c) asm("fma.rn.f32x2 %0, %1, %2, %3;" : "=l"(d) : "l"(a), "l"(b), "l"(c))
#define ADD2(d, a, b)    asm("add.rn.f32x2 %0, %1, %2;"     : "=l"(d) : "l"(a), "l"(b))

__device__ __forceinline__ float tanh_fast(float x) {
    float cx = fminf(fmaxf(x, -15.f), 15.f);
    float e = __expf(2.f * cx);
    return __fdividef(e - 1.f, e + 1.f);
}

// ---------------------------------------------------------------------------
// Table build: grid (T_TAB/8, 2), block 256.
// ---------------------------------------------------------------------------
__global__ void build_tab_kernel(const float* __restrict__ wf_ee,
                                 const float* __restrict__ bf_ee,
                                 const float* __restrict__ wf_en,
                                 const float* __restrict__ bf_en) {
    __shared__ float s_wf[FEAT * FEAT];
    __shared__ float s_rbf[8][FEAT];
    const float* wf = blockIdx.y ? wf_en : wf_ee;
    const float* bf = blockIdx.y ? bf_en : bf_ee;
    float* tab      = blockIdx.y ? g_tab_en : g_tab_ee;

    const int t = threadIdx.x;
    for (int i = t; i < FEAT * FEAT; i += 256) s_wf[i] = wf[i];

    const int f  = t & 63;
    const int rg = t >> 6;
    const int base = blockIdx.x * 8;

    #pragma unroll
    for (int rr = 0; rr < 2; rr++) {
        int r = rg + rr * 4;
        float d = (float)(base + r) * (1.0f / INV_STEP);
        float x = d - (float)f * (8.0f / 63.0f);
        s_rbf[r][f] = __expf(-x * x);
    }
    __syncthreads();

    float bfv = bf[f];
    float a0 = bfv, a1 = bfv;
    const int r0 = rg, r1 = rg + 4;
    #pragma unroll
    for (int k = 0; k < FEAT; k++) {
        float w = s_wf[k * FEAT + f];
        a0 = fmaf(s_rbf[r0][k], w, a0);
        a1 = fmaf(s_rbf[r1][k], w, a1);
    }
    tab[(base + r0) * FEAT + f] = tanhf(a0);
    tab[(base + r1) * FEAT + f] = tanhf(a1);
}

// ---------------------------------------------------------------------------
struct Smem {
    __half2 filt2[NPE * 32];      // 55,680 B (en uses first 300*32)
    float   h[NN * FEAT];         // 10,240
    float   h2[NN * FEAT];        // 10,240 (double buffer; also distance scratch)
    float4  wlT[NL * 32 * 32];    // 32,768 interleaved: [l][kk][fp] = {w[2kk][2fp],w[2kk][2fp+1],w[2kk+1][2fp],w[2kk+1][2fp+1]}
    float   bl[NL * FEAT];        // 512
    float   wr[FEAT];             // 256
    float   xyz[NE * 3];          // 360
    float   atm[NA * 3];          // 120
    float   red[NWARP];           // 64
};                                 // ~110,240 B -> 2 CTAs/SM

__device__ __forceinline__ float block_reduce(float v, float* s_red, int t) {
    #pragma unroll
    for (int o = 16; o; o >>= 1) v += __shfl_down_sync(0xffffffffu, v, o);
    if ((t & 31) == 0) s_red[t >> 5] = v;
    __syncthreads();
    if (t == 0) {
        float x = 0.f;
        #pragma unroll
        for (int w = 0; w < NWARP; w++) x += s_red[w];
        s_red[0] = x;
    }
    __syncthreads();
    float r = s_red[0];
    __syncthreads();
    return r;
}

// stage interleaved weights + bias + readout vector for one graph
__device__ __forceinline__ void stage_weights(Smem& S, const float* wl,
                                              const float* bl, const float* wr, int t) {
    for (int idx = t; idx < NL * 32 * 32; idx += BLK) {
        int l = idx >> 10, r = idx & 1023;
        int kk = r >> 5, fp = r & 31;
        const float* s0 = &wl[(l * FEAT + 2 * kk) * FEAT + 2 * fp];
        float4 v;
        v.x = s0[0]; v.y = s0[1];
        v.z = s0[FEAT]; v.w = s0[FEAT + 1];
        S.wlT[idx] = v;
    }
    for (int i = t; i < NL * FEAT; i += BLK) S.bl[i] = bl[i];
    if (t < FEAT) S.wr[t] = wr[t];
}

// linear for node pair (n0,n1); agg arrives in registers (a0,a1 per lane =
// features 2fp,2fp+1), broadcast across the warp via shfl.
__device__ __forceinline__ void linear2(Smem& S, int l, float2 a0, float2 a1,
                                        int n0, int n1, int fp,
                                        const float* hsrc, float* hdst) {
    u64 bias = *(const u64*)&S.bl[l * FEAT + 2 * fp];
    u64 c0a = bias, c0b = 0, c1a = bias, c1b = 0;
    const float4* wT = &S.wlT[l * 1024 + fp];
    #pragma unroll
    for (int kk = 0; kk < 32; kk++) {
        float4 w = wT[kk * 32];
        u64 w0 = pack2(w.x, w.y);
        u64 w1 = pack2(w.z, w.w);
        float v;
        v = __shfl_sync(0xffffffffu, a0.x, kk);
        { u64 s = pack2(v, v); FMA2(c0a, s, w0, c0a); }
        v = __shfl_sync(0xffffffffu, a0.y, kk);
        { u64 s = pack2(v, v); FMA2(c0b, s, w1, c0b); }
        v = __shfl_sync(0xffffffffu, a1.x, kk);
        { u64 s = pack2(v, v); FMA2(c1a, s, w0, c1a); }
        v = __shfl_sync(0xffffffffu, a1.y, kk);
        { u64 s = pack2(v, v); FMA2(c1b, s, w1, c1b); }
    }
    ADD2(c0a, c0a, c0b);
    ADD2(c1a, c1a, c1b);
    float2 s0 = unpack2(c0a), s1 = unpack2(c1a);
    float2 h0 = unpack2(*(const u64*)&hsrc[n0 * FEAT + 2 * fp]);
    float2 h1 = unpack2(*(const u64*)&hsrc[n1 * FEAT + 2 * fp]);
    h0.x += tanh_fast(s0.x); h0.y += tanh_fast(s0.y);
    h1.x += tanh_fast(s1.x); h1.y += tanh_fast(s1.y);
    *(u64*)&hdst[n0 * FEAT + 2 * fp] = pack2(h0.x, h0.y);
    *(u64*)&hdst[n1 * FEAT + 2 * fp] = pack2(h1.x, h1.y);
}

__global__ void __launch_bounds__(BLK, 2) jastrow_kernel(
    const float* __restrict__ pos,    const float* __restrict__ atoms,
    const float* __restrict__ emb_ee, const float* __restrict__ wl_ee,
    const float* __restrict__ bl_ee,  const float* __restrict__ wr_ee,
    const float* __restrict__ br_ee,
    const float* __restrict__ emb_en, const float* __restrict__ wl_en,
    const float* __restrict__ bl_en,  const float* __restrict__ wr_en,
    const float* __restrict__ br_en,
    float* __restrict__ out) {
    extern __shared__ char smem_raw[];
    Smem& S = *reinterpret_cast<Smem*>(smem_raw);
    float* Sd = S.h2;   // distance scratch (dead before first linear write)
    const int t = threadIdx.x;
    const int b = blockIdx.x;
    const int warp = t >> 5;
    const int fp = t & 31;

    for (int i = t; i < NE * 3; i += BLK) S.xyz[i] = pos[b * NE * 3 + i];
    for (int i = t; i < NA * 3; i += BLK) S.atm[i] = atoms[i];
    stage_weights(S, wl_ee, bl_ee, wr_ee, t);
    __syncthreads();

    // ================= EE graph =================
    for (int x = t; x < NE * NE; x += BLK) {
        int i = x / NE, j = x % NE;
        if (i < j) {
            int p = ((i * (2 * NE - 1 - i)) >> 1) + j - i - 1;
            float dx = S.xyz[i * 3 + 0] - S.xyz[j * 3 + 0];
            float dy = S.xyz[i * 3 + 1] - S.xyz[j * 3 + 1];
            float dz = S.xyz[i * 3 + 2] - S.xyz[j * 3 + 2];
            Sd[p] = sqrtf(dx * dx + dy * dy + dz * dz);
        }
    }
    __syncthreads();

    for (int it = t; it < NPE * 32; it += BLK) {
        int p = it >> 5, f2 = it & 31;
        float u = fminf(Sd[p] * INV_STEP, (float)(T_TAB - 2) + 0.999f);
        int idx = (int)u;
        float w = u - (float)idx;
        float2 v0 = *(const float2*)&g_tab_ee[idx * FEAT + 2 * f2];
        float2 v1 = *(const float2*)&g_tab_ee[(idx + 1) * FEAT + 2 * f2];
        S.filt2[it] = __floats2half2_rn(fmaf(w, v1.x - v0.x, v0.x),
                                        fmaf(w, v1.y - v0.y, v0.y));
    }
    for (int it = t; it < NE * FEAT; it += BLK) {
        int n = it >> 6, f = it & 63;
        S.h[it] = emb_ee[(n < 15 ? 0 : FEAT) + f];
    }
    __syncthreads();

    for (int l = 0; l < NL; l++) {
        const float* hsrc = l ? S.h2 : S.h;
        float*       hdst = l ? S.h  : S.h2;
        if (warp < 15) {
            const int n0 = 2 * warp, n1 = n0 + 1;
            const int Bn0 = ((n0 * (2 * NE - 1 - n0)) >> 1) - n0 - 1;
            const int Bn1 = ((n1 * (2 * NE - 1 - n1)) >> 1) - n1 - 1;
            u64 a0a = 0, a0b = 0, a1a = 0, a1b = 0;
            #pragma unroll
            for (int j = 0; j < NE; j++) {
                const int K1 = ((j * (2 * NE - 1 - j)) >> 1) - j - 1;
                u64 hv = *(const u64*)&hsrc[j * FEAT + 2 * fp];
                if (j != n0) {
                    int p = (j < n0) ? (K1 + n0) : (Bn0 + j);
                    float2 fv = __half22float2(S.filt2[p * 32 + fp]);
                    u64 f2 = pack2(fv.x, fv.y);
                    if (j & 1) { FMA2(a0b, hv, f2, a0b); } else { FMA2(a0a, hv, f2, a0a); }
                }
                if (j != n1) {
                    int p = (j < n1) ? (K1 + n1) : (Bn1 + j);
                    float2 fv = __half22float2(S.filt2[p * 32 + fp]);
                    u64 f2 = pack2(fv.x, fv.y);
                    if (j & 1) { FMA2(a1b, hv, f2, a1b); } else { FMA2(a1a, hv, f2, a1a); }
                }
            }
            ADD2(a0a, a0a, a0b);
            ADD2(a1a, a1a, a1b);
            linear2(S, l, unpack2(a0a), unpack2(a1a), n0, n1, fp, hsrc, hdst);
        }
        __syncthreads();
    }
    float acc = 0.f;
    for (int it = t; it < NE * FEAT; it += BLK) acc = fmaf(S.h[it], S.wr[it & 63], acc);
    float k_ee = block_reduce(acc, S.red, t) + br_ee[0];

    // ================= EN graph =================
    for (int q = t; q < NPN; q += BLK) {
        int a = q / NE, e = q % NE;
        float dx = S.xyz[e * 3 + 0] - S.atm[a * 3 + 0];
        float dy = S.xyz[e * 3 + 1] - S.atm[a * 3 + 1];
        float dz = S.xyz[e * 3 + 2] - S.atm[a * 3 + 2];
        Sd[q] = sqrtf(dx * dx + dy * dy + dz * dz);
    }
    stage_weights(S, wl_en, bl_en, wr_en, t);
    __syncthreads();

    for (int it = t; it < NPN * 32; it += BLK) {
        int q = it >> 5, f2 = it & 31;
        float u = fminf(Sd[q] * INV_STEP, (float)(T_TAB - 2) + 0.999f);
        int idx = (int)u;
        float w = u - (float)idx;
        float2 v0 = *(const float2*)&g_tab_en[idx * FEAT + 2 * f2];
        float2 v1 = *(const float2*)&g_tab_en[(idx + 1) * FEAT + 2 * f2];
        S.filt2[it] = __floats2half2_rn(fmaf(w, v1.x - v0.x, v0.x),
                                        fmaf(w, v1.y - v0.y, v0.y));
    }
    for (int it = t; it < NN * FEAT; it += BLK) {
        int n = it >> 6, f = it & 63;
        int ty = (n < 15) ? 0 : (n < NE ? 1 : 2 + (n - NE));
        S.h[it] = emb_en[ty * FEAT + f];
    }
    __syncthreads();

    for (int l = 0; l < NL; l++) {
        const float* hsrc = l ? S.h2 : S.h;
        float*       hdst = l ? S.h  : S.h2;
        for (int item = warp; item < 20; item += NWARP) {
            u64 a0a = 0, a0b = 0, a1a = 0, a1b = 0;
            int n0, n1;
            if (item < 15) {          // electron pair: neighbors = atoms
                n0 = 2 * item; n1 = n0 + 1;
                #pragma unroll
                for (int aa = 0; aa < NA; aa++) {
                    u64 hv = *(const u64*)&hsrc[(NE + aa) * FEAT + 2 * fp];
                    float2 f0 = __half22float2(S.filt2[(aa * NE + n0) * 32 + fp]);
                    float2 f1 = __half22float2(S.filt2[(aa * NE + n1) * 32 + fp]);
                    u64 p0 = pack2(f0.x, f0.y), p1 = pack2(f1.x, f1.y);
                    if (aa & 1) { FMA2(a0b, hv, p0, a0b); FMA2(a1b, hv, p1, a1b); }
                    else        { FMA2(a0a, hv, p0, a0a); FMA2(a1a, hv, p1, a1a); }
                }
            } else {                  // atom pair: neighbors = electrons
                int aa0 = 2 * (item - 15), aa1 = aa0 + 1;
                n0 = NE + aa0; n1 = NE + aa1;
                #pragma unroll
                for (int e = 0; e < NE; e++) {
                    u64 hv = *(const u64*)&hsrc[e * FEAT + 2 * fp];
                    float2 f0 = __half22float2(S.filt2[(aa0 * NE + e) * 32 + fp]);
                    float2 f1 = __half22float2(S.filt2[(aa1 * NE + e) * 32 + fp]);
                    u64 p0 = pack2(f0.x, f0.y), p1 = pack2(f1.x, f1.y);
                    if (e & 1) { FMA2(a0b, hv, p0, a0b); FMA2(a1b, hv, p1, a1b); }
                    else       { FMA2(a0a, hv, p0, a0a); FMA2(a1a, hv, p1, a1a); }
                }
            }
            ADD2(a0a, a0a, a0b);
            ADD2(a1a, a1a, a1b);
            linear2(S, l, unpack2(a0a), unpack2(a1a), n0, n1, fp, hsrc, hdst);
        }
        __syncthreads();
    }
    float acc2 = 0.f;
    for (int it = t; it < NN * FEAT; it += BLK) acc2 = fmaf(S.h[it], S.wr[it & 63], acc2);
    float k_en = block_reduce(acc2, S.red, t) + br_en[0];

    if (t == 0) out[b] = expf(k_ee + k_en);
}

// ---------------------------------------------------------------------------
extern "C" void kernel_launch(void* const* d_in, const int* in_sizes, int n_in,
                              void* d_out, int out_size) {
    const float* pos    = (const float*)d_in[0];
    const float* atoms  = (const float*)d_in[1];
    const float* emb_ee = (const float*)d_in[2];
    const float* wf_ee  = (const float*)d_in[3];
    const float* bf_ee  = (const float*)d_in[4];
    const float* wl_ee  = (const float*)d_in[5];
    const float* bl_ee  = (const float*)d_in[6];
    const float* wr_ee  = (const float*)d_in[7];
    const float* br_ee  = (const float*)d_in[8];
    const float* emb_en = (const float*)d_in[9];
    const float* wf_en  = (const float*)d_in[10];
    const float* bf_en  = (const float*)d_in[11];
    const float* wl_en  = (const float*)d_in[12];
    const float* bl_en  = (const float*)d_in[13];
    const float* wr_en  = (const float*)d_in[14];
    const float* br_en  = (const float*)d_in[15];
    float* out = (float*)d_out;

    int nb = in_sizes[0] / (NE * 3);

    cudaFuncSetAttribute(jastrow_kernel,
                         cudaFuncAttributeMaxDynamicSharedMemorySize,
                         (int)sizeof(Smem));

    build_tab_kernel<<<dim3(T_TAB / 8, 2), 256>>>(wf_ee, bf_ee, wf_en, bf_en);
    jastrow_kernel<<<nb, BLK, sizeof(Smem)>>>(
        pos, atoms, emb_ee, wl_ee, bl_ee, wr_ee, br_ee,
        emb_en, wl_en, bl_en, wr_en, br_en, out);
}

// round 5
// speedup vs baseline: 2.0925x; 1.1004x over previous
#include <cuda_runtime.h>
#include <cuda_fp16.h>
#include <math.h>

#define NE    30      // electrons
#define NA    10      // atoms
#define NN    40      // en-graph nodes
#define FEAT  64
#define NPE   435     // ee unique pairs
#define NPN   300     // en unique pairs
#define NL    2
#define T_TAB 4096
#define INV_STEP 256.0f   // T_TAB / 16.0 range
#define BLK   512
#define NWARP (BLK / 32)

typedef unsigned long long u64;

__device__ float g_tab_ee[T_TAB * FEAT];
__device__ float g_tab_en[T_TAB * FEAT];

// ---- packed f32x2 helpers (Blackwell) -------------------------------------
__device__ __forceinline__ u64 pack2(float x, float y) {
    u64 r; asm("mov.b64 %0, {%1,%2};" : "=l"(r) : "f"(x), "f"(y)); return r;
}
__device__ __forceinline__ float2 unpack2(u64 v) {
    float2 f; asm("mov.b64 {%0,%1}, %2;" : "=f"(f.x), "=f"(f.y) : "l"(v)); return f;
}
#define FMA2(d, a, b, c) asm("fma.rn.f32x2 %0, %1, %2, %3;" : "=l"(d) : "l"(a), "l"(b), "l"(c))
#define ADD2(d, a, b)    asm("add.rn.f32x2 %0, %1, %2;"     : "=l"(d) : "l"(a), "l"(b))

__device__ __forceinline__ float tanh_fast(float x) {
    float cx = fminf(fmaxf(x, -15.f), 15.f);
    float e = __expf(2.f * cx);
    return __fdividef(e - 1.f, e + 1.f);
}

// ---------------------------------------------------------------------------
// Table build: grid (T_TAB/8, 2), block 256.
// ---------------------------------------------------------------------------
__global__ void build_tab_kernel(const float* __restrict__ wf_ee,
                                 const float* __restrict__ bf_ee,
                                 const float* __restrict__ wf_en,
                                 const float* __restrict__ bf_en) {
    __shared__ float s_wf[FEAT * FEAT];
    __shared__ float s_rbf[8][FEAT];
    const float* wf = blockIdx.y ? wf_en : wf_ee;
    const float* bf = blockIdx.y ? bf_en : bf_ee;
    float* tab      = blockIdx.y ? g_tab_en : g_tab_ee;

    const int t = threadIdx.x;
    for (int i = t; i < FEAT * FEAT; i += 256) s_wf[i] = wf[i];

    const int f  = t & 63;
    const int rg = t >> 6;
    const int base = blockIdx.x * 8;

    #pragma unroll
    for (int rr = 0; rr < 2; rr++) {
        int r = rg + rr * 4;
        float d = (float)(base + r) * (1.0f / INV_STEP);
        float x = d - (float)f * (8.0f / 63.0f);
        s_rbf[r][f] = __expf(-x * x);
    }
    __syncthreads();

    float bfv = bf[f];
    float a0 = bfv, a1 = bfv;
    const int r0 = rg, r1 = rg + 4;
    #pragma unroll
    for (int k = 0; k < FEAT; k++) {
        float w = s_wf[k * FEAT + f];
        a0 = fmaf(s_rbf[r0][k], w, a0);
        a1 = fmaf(s_rbf[r1][k], w, a1);
    }
    tab[(base + r0) * FEAT + f] = tanhf(a0);
    tab[(base + r1) * FEAT + f] = tanhf(a1);
}

// ---------------------------------------------------------------------------
struct __align__(16) Smem {
    __half2 filt2[NPE * 32];      // 55,680 B (en uses first 300*32)
    float   h[NN * FEAT];         // 10,240 (updated in place)
    float   agg[NN * FEAT];       // 10,240 (also distance scratch)
    float4  wlT[NL * 32 * 32];    // 32,768: [l][kk][fp] = {w[2kk][2fp],w[2kk][2fp+1],w[2kk+1][2fp],w[2kk+1][2fp+1]}
    float   bl[NL * FEAT];        // 512
    float   wr[FEAT];             // 256
    float   xyz[NE * 3];          // 360
    float   atm[NA * 3];          // 120
    float   red[NWARP];           // 64
};                                 // ~110,240 B -> 2 CTAs/SM

__device__ __forceinline__ float block_reduce(float v, float* s_red, int t) {
    #pragma unroll
    for (int o = 16; o; o >>= 1) v += __shfl_down_sync(0xffffffffu, v, o);
    if ((t & 31) == 0) s_red[t >> 5] = v;
    __syncthreads();
    if (t == 0) {
        float x = 0.f;
        #pragma unroll
        for (int w = 0; w < NWARP; w++) x += s_red[w];
        s_red[0] = x;
    }
    __syncthreads();
    float r = s_red[0];
    __syncthreads();
    return r;
}

__device__ __forceinline__ void stage_weights(Smem& S, const float* wl,
                                              const float* bl, const float* wr, int t) {
    for (int idx = t; idx < NL * 32 * 32; idx += BLK) {
        int l = idx >> 10, r = idx & 1023;
        int kk = r >> 5, fp = r & 31;
        const float* s0 = &wl[(l * FEAT + 2 * kk) * FEAT + 2 * fp];
        float4 v;
        v.x = s0[0]; v.y = s0[1];
        v.z = s0[FEAT]; v.w = s0[FEAT + 1];
        S.wlT[idx] = v;
    }
    for (int i = t; i < NL * FEAT; i += BLK) S.bl[i] = bl[i];
    if (t < FEAT) S.wr[t] = wr[t];
}

// linear for up to 4 nodes [base, nlim): h[n] += tanh(agg[n] @ wl + bl), in place.
// agg read via broadcast float4 LDS; weights shared across all 4 nodes.
__device__ __forceinline__ void linear4(Smem& S, int l, int base, int nlim, int fp) {
    u64 bias = *(const u64*)&S.bl[l * FEAT + 2 * fp];
    u64 ca[4], cb[4];
    #pragma unroll
    for (int s = 0; s < 4; s++) { ca[s] = bias; cb[s] = 0; }
    const float4* wT = &S.wlT[l * 1024 + fp];
    #pragma unroll
    for (int kk = 0; kk < 32; kk += 2) {
        float4 w0 = wT[kk * 32];
        float4 w1 = wT[(kk + 1) * 32];
        u64 w0a = pack2(w0.x, w0.y), w0b = pack2(w0.z, w0.w);
        u64 w1a = pack2(w1.x, w1.y), w1b = pack2(w1.z, w1.w);
        #pragma unroll
        for (int s = 0; s < 4; s++) {
            int n = base + s;
            if (n < nlim) {
                float4 av = *(const float4*)&S.agg[n * FEAT + 2 * kk];  // broadcast
                u64 d;
                d = pack2(av.x, av.x); FMA2(ca[s], d, w0a, ca[s]);
                d = pack2(av.y, av.y); FMA2(cb[s], d, w0b, cb[s]);
                d = pack2(av.z, av.z); FMA2(ca[s], d, w1a, ca[s]);
                d = pack2(av.w, av.w); FMA2(cb[s], d, w1b, cb[s]);
            }
        }
    }
    #pragma unroll
    for (int s = 0; s < 4; s++) {
        int n = base + s;
        if (n < nlim) {
            ADD2(ca[s], ca[s], cb[s]);
            float2 sv = unpack2(ca[s]);
            float2 hv = unpack2(*(const u64*)&S.h[n * FEAT + 2 * fp]);
            hv.x += tanh_fast(sv.x);
            hv.y += tanh_fast(sv.y);
            *(u64*)&S.h[n * FEAT + 2 * fp] = pack2(hv.x, hv.y);
        }
    }
}

__global__ void __launch_bounds__(BLK, 2) jastrow_kernel(
    const float* __restrict__ pos,    const float* __restrict__ atoms,
    const float* __restrict__ emb_ee, const float* __restrict__ wl_ee,
    const float* __restrict__ bl_ee,  const float* __restrict__ wr_ee,
    const float* __restrict__ br_ee,
    const float* __restrict__ emb_en, const float* __restrict__ wl_en,
    const float* __restrict__ bl_en,  const float* __restrict__ wr_en,
    const float* __restrict__ br_en,
    float* __restrict__ out) {
    extern __shared__ char smem_raw[];
    Smem& S = *reinterpret_cast<Smem*>(smem_raw);
    float* Sd = S.agg;   // distance scratch (dead during layer loops' agg use? no:
                         // distances consumed into filt2 before first gather)
    const int t = threadIdx.x;
    const int b = blockIdx.x;
    const int warp = t >> 5;
    const int fp = t & 31;

    for (int i = t; i < NE * 3; i += BLK) S.xyz[i] = pos[b * NE * 3 + i];
    for (int i = t; i < NA * 3; i += BLK) S.atm[i] = atoms[i];
    stage_weights(S, wl_ee, bl_ee, wr_ee, t);
    __syncthreads();

    // ================= EE graph =================
    for (int x = t; x < NE * NE; x += BLK) {
        int i = x / NE, j = x % NE;
        if (i < j) {
            int p = ((i * (2 * NE - 1 - i)) >> 1) + j - i - 1;
            float dx = S.xyz[i * 3 + 0] - S.xyz[j * 3 + 0];
            float dy = S.xyz[i * 3 + 1] - S.xyz[j * 3 + 1];
            float dz = S.xyz[i * 3 + 2] - S.xyz[j * 3 + 2];
            Sd[p] = sqrtf(dx * dx + dy * dy + dz * dz);
        }
    }
    __syncthreads();

    for (int it = t; it < NPE * 32; it += BLK) {
        int p = it >> 5, f2 = it & 31;
        float u = fminf(Sd[p] * INV_STEP, (float)(T_TAB - 2) + 0.999f);
        int idx = (int)u;
        float w = u - (float)idx;
        float2 v0 = *(const float2*)&g_tab_ee[idx * FEAT + 2 * f2];
        float2 v1 = *(const float2*)&g_tab_ee[(idx + 1) * FEAT + 2 * f2];
        S.filt2[it] = __floats2half2_rn(fmaf(w, v1.x - v0.x, v0.x),
                                        fmaf(w, v1.y - v0.y, v0.y));
    }
    for (int it = t; it < NE * FEAT; it += BLK) {
        int n = it >> 6, f = it & 63;
        S.h[it] = emb_ee[(n < 15 ? 0 : FEAT) + f];
    }
    __syncthreads();

    for (int l = 0; l < NL; l++) {
        // gather: warps 0-7, 4 nodes each (warp 7: 2 nodes)
        if (warp < 8) {
            const int base = 4 * warp;
            u64 acc[4] = {0, 0, 0, 0};
            int Bn[4];
            #pragma unroll
            for (int s = 0; s < 4; s++) {
                int n = base + s;
                Bn[s] = (n < NE) ? (((n * (2 * NE - 1 - n)) >> 1) - n - 1) : 0;
            }
            #pragma unroll
            for (int j = 0; j < NE; j++) {
                const int K1 = ((j * (2 * NE - 1 - j)) >> 1) - j - 1;
                u64 hv = *(const u64*)&S.h[j * FEAT + 2 * fp];
                #pragma unroll
                for (int s = 0; s < 4; s++) {
                    int n = base + s;
                    if (n < NE && j != n) {
                        int p = (j < n) ? (K1 + n) : (Bn[s] + j);
                        float2 fv = __half22float2(S.filt2[p * 32 + fp]);
                        u64 f2 = pack2(fv.x, fv.y);
                        FMA2(acc[s], hv, f2, acc[s]);
                    }
                }
            }
            #pragma unroll
            for (int s = 0; s < 4; s++) {
                int n = base + s;
                if (n < NE) *(u64*)&S.agg[n * FEAT + 2 * fp] = acc[s];
            }
        }
        __syncthreads();
        if (warp < 8) linear4(S, l, 4 * warp, NE, fp);
        __syncthreads();
    }
    float acc = 0.f;
    for (int it = t; it < NE * FEAT; it += BLK) acc = fmaf(S.h[it], S.wr[it & 63], acc);
    float k_ee = block_reduce(acc, S.red, t) + br_ee[0];

    // ================= EN graph =================
    for (int q = t; q < NPN; q += BLK) {
        int a = q / NE, e = q % NE;
        float dx = S.xyz[e * 3 + 0] - S.atm[a * 3 + 0];
        float dy = S.xyz[e * 3 + 1] - S.atm[a * 3 + 1];
        float dz = S.xyz[e * 3 + 2] - S.atm[a * 3 + 2];
        Sd[q] = sqrtf(dx * dx + dy * dy + dz * dz);
    }
    stage_weights(S, wl_en, bl_en, wr_en, t);
    __syncthreads();

    for (int it = t; it < NPN * 32; it += BLK) {
        int q = it >> 5, f2 = it & 31;
        float u = fminf(Sd[q] * INV_STEP, (float)(T_TAB - 2) + 0.999f);
        int idx = (int)u;
        float w = u - (float)idx;
        float2 v0 = *(const float2*)&g_tab_en[idx * FEAT + 2 * f2];
        float2 v1 = *(const float2*)&g_tab_en[(idx + 1) * FEAT + 2 * f2];
        S.filt2[it] = __floats2half2_rn(fmaf(w, v1.x - v0.x, v0.x),
                                        fmaf(w, v1.y - v0.y, v0.y));
    }
    for (int it = t; it < NN * FEAT; it += BLK) {
        int n = it >> 6, f = it & 63;
        int ty = (n < 15) ? 0 : (n < NE ? 1 : 2 + (n - NE));
        S.h[it] = emb_en[ty * FEAT + f];
    }
    __syncthreads();

    for (int l = 0; l < NL; l++) {
        // gather: warps 0-7 electrons (4 each; warp 7: 2),
        //         warps 8-10 atoms (4,4,2)
        if (warp < 8) {
            const int base = 4 * warp;
            u64 acc[4] = {0, 0, 0, 0};
            #pragma unroll
            for (int aa = 0; aa < NA; aa++) {
                u64 hv = *(const u64*)&S.h[(NE + aa) * FEAT + 2 * fp];
                #pragma unroll
                for (int s = 0; s < 4; s++) {
                    int n = base + s;
                    if (n < NE) {
                        float2 fv = __half22float2(S.filt2[(aa * NE + n) * 32 + fp]);
                        u64 f2 = pack2(fv.x, fv.y);
                        FMA2(acc[s], hv, f2, acc[s]);
                    }
                }
            }
            #pragma unroll
            for (int s = 0; s < 4; s++) {
                int n = base + s;
                if (n < NE) *(u64*)&S.agg[n * FEAT + 2 * fp] = acc[s];
            }
        } else if (warp < 11) {
            const int abase = 4 * (warp - 8);
            u64 acc[4] = {0, 0, 0, 0};
            #pragma unroll
            for (int e = 0; e < NE; e++) {
                u64 hv = *(const u64*)&S.h[e * FEAT + 2 * fp];
                #pragma unroll
                for (int s = 0; s < 4; s++) {
                    int a = abase + s;
                    if (a < NA) {
                        float2 fv = __half22float2(S.filt2[(a * NE + e) * 32 + fp]);
                        u64 f2 = pack2(fv.x, fv.y);
                        FMA2(acc[s], hv, f2, acc[s]);
                    }
                }
            }
            #pragma unroll
            for (int s = 0; s < 4; s++) {
                int a = abase + s;
                if (a < NA) *(u64*)&S.agg[(NE + a) * FEAT + 2 * fp] = acc[s];
            }
        }
        __syncthreads();
        if (warp < 10) linear4(S, l, 4 * warp, NN, fp);
        __syncthreads();
    }
    float acc2 = 0.f;
    for (int it = t; it < NN * FEAT; it += BLK) acc2 = fmaf(S.h[it], S.wr[it & 63], acc2);
    float k_en = block_reduce(acc2, S.red, t) + br_en[0];

    if (t == 0) out[b] = expf(k_ee + k_en);
}

// ---------------------------------------------------------------------------
extern "C" void kernel_launch(void* const* d_in, const int* in_sizes, int n_in,
                              void* d_out, int out_size) {
    const float* pos    = (const float*)d_in[0];
    const float* atoms  = (const float*)d_in[1];
    const float* emb_ee = (const float*)d_in[2];
    const float* wf_ee  = (const float*)d_in[3];
    const float* bf_ee  = (const float*)d_in[4];
    const float* wl_ee  = (const float*)d_in[5];
    const float* bl_ee  = (const float*)d_in[6];
    const float* wr_ee  = (const float*)d_in[7];
    const float* br_ee  = (const float*)d_in[8];
    const float* emb_en = (const float*)d_in[9];
    const float* wf_en  = (const float*)d_in[10];
    const float* bf_en  = (const float*)d_in[11];
    const float* wl_en  = (const float*)d_in[12];
    const float* bl_en  = (const float*)d_in[13];
    const float* wr_en  = (const float*)d_in[14];
    const float* br_en  = (const float*)d_in[15];
    float* out = (float*)d_out;

    int nb = in_sizes[0] / (NE * 3);

    cudaFuncSetAttribute(jastrow_kernel,
                         cudaFuncAttributeMaxDynamicSharedMemorySize,
                         (int)sizeof(Smem));

    build_tab_kernel<<<dim3(T_TAB / 8, 2), 256>>>(wf_ee, bf_ee, wf_en, bf_en);
    jastrow_kernel<<<nb, BLK, sizeof(Smem)>>>(
        pos, atoms, emb_ee, wl_ee, bl_ee, wr_ee, br_ee,
        emb_en, wl_en, bl_en, wr_en, br_en, out);
}